// round 3
// baseline (speedup 1.0000x reference)
#include <cuda_runtime.h>
#include <cuda_bf16.h>

// Problem constants (fixed by the reference)
#define NNODES 50000
#define NEDGES 800000
#define NFEAT  512
#define NHID   256
#define NLAT   128

// ---------------- scratch (device globals; no allocation allowed) -----------
static __device__ float g_C1[(size_t)NNODES * NHID];   // x@W1            51.2 MB
static __device__ float g_H [(size_t)NNODES * NHID];   // relu(spmm1+b1)  51.2 MB
static __device__ float g_C2[(size_t)NNODES * NLAT];   // h@W2            25.6 MB
static __device__ int   g_rowptr[NNODES + 1];
static __device__ int   g_cnt[NNODES];
static __device__ int   g_cols[NEDGES];
static __device__ float g_vals[NEDGES];

// ---------------- CSR build --------------------------------------------------
__global__ void zero_cnt_kernel() {
    int i = blockIdx.x * blockDim.x + threadIdx.x;
    if (i < NNODES) g_cnt[i] = 0;
}

__global__ void hist_kernel(const int* __restrict__ rows) {
    int e = blockIdx.x * blockDim.x + threadIdx.x;
    if (e < NEDGES) atomicAdd(&g_cnt[rows[e]], 1);
}

// Single-block exclusive scan of g_cnt -> g_rowptr, also resets g_cnt (cursor).
__global__ void scan_kernel() {
    __shared__ int sums[256];
    int tid = threadIdx.x;
    const int chunk = (NNODES + 255) / 256;
    int s0 = tid * chunk;
    int s1 = min(s0 + chunk, NNODES);
    int s = 0;
    for (int i = s0; i < s1; i++) s += g_cnt[i];
    sums[tid] = s;
    __syncthreads();
    if (tid == 0) {
        int acc = 0;
        for (int i = 0; i < 256; i++) { int t = sums[i]; sums[i] = acc; acc += t; }
        g_rowptr[NNODES] = acc;
    }
    __syncthreads();
    int acc = sums[tid];
    for (int i = s0; i < s1; i++) {
        g_rowptr[i] = acc;
        acc += g_cnt[i];
        g_cnt[i] = 0;   // reset as scatter cursor
    }
}

__global__ void scatter_kernel(const int* __restrict__ rows, const int* __restrict__ cols,
                               const float* __restrict__ vals) {
    int e = blockIdx.x * blockDim.x + threadIdx.x;
    if (e >= NEDGES) return;
    int r = rows[e];
    int p = g_rowptr[r] + atomicAdd(&g_cnt[r], 1);
    g_cols[p] = cols[e];
    g_vals[p] = vals[e];
}

// ---------------- SGEMM (fp32, row-major A[MxK] * B[KxN] = C[MxN]) ----------
#define BM 128
#define BN 64
#define BKK 16

__global__ __launch_bounds__(256) void sgemm_kernel(
    const float* __restrict__ A, const float* __restrict__ B, float* __restrict__ C,
    int M, int N, int K)
{
    __shared__ float As[BKK][BM];   // transposed A tile
    __shared__ float Bs[BKK][BN];

    int tid = threadIdx.x;           // 256 threads
    int bm = blockIdx.y * BM;
    int bn = blockIdx.x * BN;
    int ty = tid >> 4;               // 0..15 -> 8 rows each
    int tx = tid & 15;               // 0..15 -> 4 cols each

    float acc[8][4];
#pragma unroll
    for (int i = 0; i < 8; i++)
#pragma unroll
        for (int j = 0; j < 4; j++) acc[i][j] = 0.f;

    int ar = tid >> 2;               // 0..63
    int ac = (tid & 3) << 2;         // 0,4,8,12
    int br = tid >> 4;               // 0..15
    int bc = (tid & 15) << 2;        // 0..60

    for (int k0 = 0; k0 < K; k0 += BKK) {
        float4 a0 = make_float4(0.f, 0.f, 0.f, 0.f);
        float4 a1 = a0;
        int r0 = bm + ar;
        int r1 = r0 + 64;
        if (r0 < M) a0 = *(const float4*)&A[(size_t)r0 * K + k0 + ac];
        if (r1 < M) a1 = *(const float4*)&A[(size_t)r1 * K + k0 + ac];
        float4 bv = *(const float4*)&B[(size_t)(k0 + br) * N + bn + bc];

        As[ac + 0][ar] = a0.x;
        As[ac + 1][ar] = a0.y;
        As[ac + 2][ar] = a0.z;
        As[ac + 3][ar] = a0.w;
        As[ac + 0][ar + 64] = a1.x;
        As[ac + 1][ar + 64] = a1.y;
        As[ac + 2][ar + 64] = a1.z;
        As[ac + 3][ar + 64] = a1.w;
        *(float4*)&Bs[br][bc] = bv;
        __syncthreads();

#pragma unroll
        for (int k = 0; k < BKK; k++) {
            float4 av0 = *(const float4*)&As[k][ty * 8];
            float4 av1 = *(const float4*)&As[k][ty * 8 + 4];
            float4 bv2 = *(const float4*)&Bs[k][tx * 4];
            float a[8] = {av0.x, av0.y, av0.z, av0.w, av1.x, av1.y, av1.z, av1.w};
            float b[4] = {bv2.x, bv2.y, bv2.z, bv2.w};
#pragma unroll
            for (int i = 0; i < 8; i++)
#pragma unroll
                for (int j = 0; j < 4; j++)
                    acc[i][j] = fmaf(a[i], b[j], acc[i][j]);
        }
        __syncthreads();
    }

#pragma unroll
    for (int i = 0; i < 8; i++) {
        int r = bm + ty * 8 + i;
        if (r < M) {
            float4 o = make_float4(acc[i][0], acc[i][1], acc[i][2], acc[i][3]);
            *(float4*)&C[(size_t)r * N + bn + tx * 4] = o;
        }
    }
}

// ---------------- CSR SpMM with fused bias+relu -----------------------------
// One warp per output row; register accumulation (no atomics).
// One-deep software pipeline on the (col, val) edge stream to hide index-load
// latency behind the dense-row gather+FMA pass.
// NP = number of 128-float passes (d = NP*128).
template <int NP>
__global__ __launch_bounds__(256) void spmm_kernel(
    const float* __restrict__ dense, const float* __restrict__ bias,
    float* __restrict__ out)
{
    int gw = (blockIdx.x * blockDim.x + threadIdx.x) >> 5;
    int lane = threadIdx.x & 31;
    if (gw >= NNODES) return;
    const int d = NP * 128;

    int beg = g_rowptr[gw];
    int end = g_rowptr[gw + 1];

    float4 acc[NP];
#pragma unroll
    for (int p = 0; p < NP; p++) acc[p] = make_float4(0.f, 0.f, 0.f, 0.f);

    if (beg < end) {
        int   c = __ldg(&g_cols[beg]);
        float v = __ldg(&g_vals[beg]);
        for (int e = beg; e < end; e++) {
            int   cn = 0;
            float vn = 0.f;
            if (e + 1 < end) {              // prefetch next edge
                cn = __ldg(&g_cols[e + 1]);
                vn = __ldg(&g_vals[e + 1]);
            }
            const float4* src = (const float4*)&dense[(size_t)c * d];
#pragma unroll
            for (int p = 0; p < NP; p++) {
                float4 t = __ldg(&src[lane + 32 * p]);
                acc[p].x = fmaf(v, t.x, acc[p].x);
                acc[p].y = fmaf(v, t.y, acc[p].y);
                acc[p].z = fmaf(v, t.z, acc[p].z);
                acc[p].w = fmaf(v, t.w, acc[p].w);
            }
            c = cn;
            v = vn;
        }
    }

    const float4* bp = (const float4*)bias;
    float4* op = (float4*)&out[(size_t)gw * d];
#pragma unroll
    for (int p = 0; p < NP; p++) {
        float4 b = __ldg(&bp[lane + 32 * p]);
        float4 r;
        r.x = fmaxf(acc[p].x + b.x, 0.f);
        r.y = fmaxf(acc[p].y + b.y, 0.f);
        r.z = fmaxf(acc[p].z + b.z, 0.f);
        r.w = fmaxf(acc[p].w + b.w, 0.f);
        op[lane + 32 * p] = r;
    }
}

// ---------------- launch -----------------------------------------------------
extern "C" void kernel_launch(void* const* d_in, const int* in_sizes, int n_in,
                              void* d_out, int out_size)
{
    const float* x    = (const float*)d_in[0];
    const int*   rows = (const int*)  d_in[1];
    const int*   cols = (const int*)  d_in[2];
    const float* vals = (const float*)d_in[3];
    const float* W1   = (const float*)d_in[4];
    const float* b1   = (const float*)d_in[5];
    const float* W2   = (const float*)d_in[6];
    const float* b2   = (const float*)d_in[7];
    float* out = (float*)d_out;

    (void)in_sizes; (void)n_in; (void)out_size;

    // CSR build (cheap)
    zero_cnt_kernel<<<(NNODES + 255) / 256, 256>>>();
    hist_kernel<<<(NEDGES + 255) / 256, 256>>>(rows);
    scan_kernel<<<1, 256>>>();
    scatter_kernel<<<(NEDGES + 255) / 256, 256>>>(rows, cols, vals);

    // Layer 1: C1 = x @ W1 ; H = relu(spmm(C1) + b1)
    {
        dim3 grid(NHID / BN, (NNODES + BM - 1) / BM);
        sgemm_kernel<<<grid, 256>>>(x, W1, g_C1, NNODES, NHID, NFEAT);
    }
    spmm_kernel<2><<<(NNODES * 32 + 255) / 256, 256>>>(g_C1, b1, g_H);

    // Layer 2: C2 = H @ W2 ; out = relu(spmm(C2) + b2)
    {
        dim3 grid(NLAT / BN, (NNODES + BM - 1) / BM);
        sgemm_kernel<<<grid, 256>>>(g_H, W2, g_C2, NNODES, NLAT, NHID);
    }
    spmm_kernel<1><<<(NNODES * 32 + 255) / 256, 256>>>(g_C2, b2, out);
}